// round 12
// baseline (speedup 1.0000x reference)
#include <cuda_runtime.h>
#include <stdint.h>

#define P1 2654435761u
#define P2 805459861u

// Table gather with 128B line-granular L2 fill (R11: small measured win).
__device__ __forceinline__ float4 ldg_tab128(const float4* p) {
    float4 v;
    asm volatile("ld.global.nc.L2::128B.v4.f32 {%0,%1,%2,%3}, [%4];"
                 : "=f"(v.x), "=f"(v.y), "=f"(v.z), "=f"(v.w) : "l"(p));
    return v;
}
// Streaming (evict-first) accessors for pts/out.
__device__ __forceinline__ float ldg_stream(const float* p) {
    float v;
    asm volatile("ld.global.cs.f32 %0, [%1];" : "=f"(v) : "l"(p));
    return v;
}
__device__ __forceinline__ void stg_stream(float4* p, float4 v) {
    asm volatile("st.global.cs.v4.f32 [%0], {%1,%2,%3,%4};"
                 :: "l"(p), "f"(v.x), "f"(v.y), "f"(v.z), "f"(v.w) : "memory");
}

// Pair-lane layout (measured best) x 2 points per thread for 16 in-flight
// gathers: R11 showed no pipe >64% => latency-bound; this raises MLP ~1.55x.
// lane 2k+h serves points (gwarp*32 + k) and (+16), half h of each 32B row.
template <bool POW2>
__global__ __launch_bounds__(256, 4)
void hash_interp_mlp2(const float* __restrict__ pts,
                      const float* __restrict__ feat,
                      float* __restrict__ out,
                      int n, unsigned buckets, unsigned mask)
{
    const unsigned lane = threadIdx.x & 31u;
    const int gwarp = (int)((blockIdx.x * blockDim.x + threadIdx.x) >> 5);
    const unsigned h = lane & 1u;

    const float4* fbase = reinterpret_cast<const float4*>(feat);

    int pid[2];
    pid[0] = gwarp * 32 + (int)(lane >> 1);
    pid[1] = pid[0] + 16;

    unsigned slot[2][8];
    float w[2][8];
    bool pvalid[2];

#pragma unroll
    for (int j = 0; j < 2; j++) {
        const bool valid = (pid[j] < n);
        pvalid[j] = valid;
        const int p = valid ? pid[j] : 0;

        const float px = ldg_stream(pts + 3 * (size_t)p + 0);
        const float py = ldg_stream(pts + 3 * (size_t)p + 1);
        const float pz = ldg_stream(pts + 3 * (size_t)p + 2);

        // continuous grid coords, matching reference's pts / 0.005
        const float qx = px / 0.005f;
        const float qy = py / 0.005f;
        const float qz = pz / 0.005f;

        const float bxf = floorf(qx);
        const float byf = floorf(qy);
        const float bzf = floorf(qz);
        const int bx = (int)bxf, by = (int)byf, bz = (int)bzf;

        const float fx = qx - bxf;
        const float fy = qy - byf;
        const float fz = qz - bzf;

        const unsigned hx0 = (unsigned)bx;
        const unsigned hx1 = (unsigned)(bx + 1);
        const unsigned hy0 = (unsigned)by * P1;
        const unsigned hy1 = hy0 + P1;
        const unsigned hz0 = (unsigned)bz * P2;
        const unsigned hz1 = hz0 + P2;

        const unsigned s0 = hx0 ^ hy0 ^ hz0;
        const unsigned s1 = hx1 ^ hy0 ^ hz0;
        const unsigned s2 = hx0 ^ hy1 ^ hz0;
        const unsigned s3 = hx1 ^ hy1 ^ hz0;
        const unsigned s4 = hx0 ^ hy0 ^ hz1;
        const unsigned s5 = hx1 ^ hy0 ^ hz1;
        const unsigned s6 = hx0 ^ hy1 ^ hz1;
        const unsigned s7 = hx1 ^ hy1 ^ hz1;
        if (POW2) {
            slot[j][0] = s0 & mask; slot[j][1] = s1 & mask;
            slot[j][2] = s2 & mask; slot[j][3] = s3 & mask;
            slot[j][4] = s4 & mask; slot[j][5] = s5 & mask;
            slot[j][6] = s6 & mask; slot[j][7] = s7 & mask;
        } else {
            slot[j][0] = s0 % buckets; slot[j][1] = s1 % buckets;
            slot[j][2] = s2 % buckets; slot[j][3] = s3 % buckets;
            slot[j][4] = s4 % buckets; slot[j][5] = s5 % buckets;
            slot[j][6] = s6 % buckets; slot[j][7] = s7 % buckets;
        }

        const float wx0 = 1.0f - fx, wx1 = fx;
        const float wy0 = 1.0f - fy, wy1 = fy;
        const float wz0 = 1.0f - fz, wz1 = fz;
        w[j][0] = wx0 * wy0 * wz0;
        w[j][1] = wx1 * wy0 * wz0;
        w[j][2] = wx0 * wy1 * wz0;
        w[j][3] = wx1 * wy1 * wz0;
        w[j][4] = wx0 * wy0 * wz1;
        w[j][5] = wx1 * wy0 * wz1;
        w[j][6] = wx0 * wy1 * wz1;
        w[j][7] = wx1 * wy1 * wz1;
    }

    // issue all 16 gathers before any consumption — 2x the in-flight misses
    float4 v[2][8];
#pragma unroll
    for (int j = 0; j < 2; j++) {
#pragma unroll
        for (int c = 0; c < 8; c++) {
            v[j][c] = ldg_tab128(fbase + ((size_t)slot[j][c] * 2 + h));
        }
    }

#pragma unroll
    for (int j = 0; j < 2; j++) {
        float a0 = 0.f, a1 = 0.f, a2 = 0.f, a3 = 0.f;
#pragma unroll
        for (int c = 0; c < 8; c++) {
            const float wc = w[j][c];
            a0 = fmaf(wc, v[j][c].x, a0);
            a1 = fmaf(wc, v[j][c].y, a1);
            a2 = fmaf(wc, v[j][c].z, a2);
            a3 = fmaf(wc, v[j][c].w, a3);
        }
        if (pvalid[j]) {
            stg_stream(reinterpret_cast<float4*>(out) + ((size_t)pid[j] * 2 + h),
                       make_float4(a0, a1, a2, a3));
        }
    }
}

extern "C" void kernel_launch(void* const* d_in, const int* in_sizes, int n_in,
                              void* d_out, int out_size)
{
    const float* pts  = (const float*)d_in[0];
    const float* feat = (const float*)d_in[1];
    float* out = (float*)d_out;

    int n = in_sizes[0] / 3;
    unsigned buckets = (unsigned)(in_sizes[1] / 8);
    unsigned mask = buckets - 1u;
    bool pow2 = (buckets & (buckets - 1u)) == 0u;

    // 2 lanes/point, 2 points/thread -> 32 points per warp
    long long warps = ((long long)n + 31) / 32;
    long long threads_total = warps * 32;
    int threads = 256;
    int blocks = (int)((threads_total + threads - 1) / threads);

    if (pow2) {
        hash_interp_mlp2<true><<<blocks, threads>>>(pts, feat, out, n, buckets, mask);
    } else {
        hash_interp_mlp2<false><<<blocks, threads>>>(pts, feat, out, n, buckets, mask);
    }
}

// round 13
// speedup vs baseline: 1.3802x; 1.3802x over previous
#include <cuda_runtime.h>
#include <stdint.h>

#define P1 2654435761u
#define P2 805459861u

__device__ __forceinline__ float4 ldg_tab128(const float4* p) {
    float4 v;
    asm volatile("ld.global.nc.L2::128B.v4.f32 {%0,%1,%2,%3}, [%4];"
                 : "=f"(v.x), "=f"(v.y), "=f"(v.z), "=f"(v.w) : "l"(p));
    return v;
}
__device__ __forceinline__ float ldg_stream(const float* p) {
    float v;
    asm volatile("ld.global.cs.f32 %0, [%1];" : "=f"(v) : "l"(p));
    return v;
}
__device__ __forceinline__ void stg_stream(float4* p, float4 v) {
    asm volatile("st.global.cs.v4.f32 [%0], {%1,%2,%3,%4};"
                 :: "l"(p), "f"(v.x), "f"(v.y), "f"(v.z), "f"(v.w) : "memory");
}
__device__ __forceinline__ void prefetch_l2(const void* p) {
    asm volatile("prefetch.global.L2 [%0];" :: "l"(p));
}

// Computes the 8 corner slots and frac coords for one point.
template <bool POW2>
__device__ __forceinline__ void point_setup(const float* pts, int p,
                                            unsigned buckets, unsigned mask,
                                            unsigned slot[8],
                                            float& fx, float& fy, float& fz)
{
    const float px = ldg_stream(pts + 3 * (size_t)p + 0);
    const float py = ldg_stream(pts + 3 * (size_t)p + 1);
    const float pz = ldg_stream(pts + 3 * (size_t)p + 2);

    const float qx = px / 0.005f;
    const float qy = py / 0.005f;
    const float qz = pz / 0.005f;

    const float bxf = floorf(qx);
    const float byf = floorf(qy);
    const float bzf = floorf(qz);
    const int bx = (int)bxf, by = (int)byf, bz = (int)bzf;

    fx = qx - bxf; fy = qy - byf; fz = qz - bzf;

    const unsigned hx0 = (unsigned)bx;
    const unsigned hx1 = (unsigned)(bx + 1);
    const unsigned hy0 = (unsigned)by * P1;
    const unsigned hy1 = hy0 + P1;
    const unsigned hz0 = (unsigned)bz * P2;
    const unsigned hz1 = hz0 + P2;

    const unsigned s0 = hx0 ^ hy0 ^ hz0;
    const unsigned s1 = hx1 ^ hy0 ^ hz0;
    const unsigned s2 = hx0 ^ hy1 ^ hz0;
    const unsigned s3 = hx1 ^ hy1 ^ hz0;
    const unsigned s4 = hx0 ^ hy0 ^ hz1;
    const unsigned s5 = hx1 ^ hy0 ^ hz1;
    const unsigned s6 = hx0 ^ hy1 ^ hz1;
    const unsigned s7 = hx1 ^ hy1 ^ hz1;
    if (POW2) {
        slot[0] = s0 & mask; slot[1] = s1 & mask; slot[2] = s2 & mask; slot[3] = s3 & mask;
        slot[4] = s4 & mask; slot[5] = s5 & mask; slot[6] = s6 & mask; slot[7] = s7 & mask;
    } else {
        slot[0] = s0 % buckets; slot[1] = s1 % buckets; slot[2] = s2 % buckets; slot[3] = s3 % buckets;
        slot[4] = s4 % buckets; slot[5] = s5 % buckets; slot[6] = s6 % buckets; slot[7] = s7 % buckets;
    }
}

// Gather + weight + accumulate + store for one point (pair-lane half h).
__device__ __forceinline__ void point_consume(const float4* fbase, float4* outp,
                                              const unsigned slot[8], unsigned h,
                                              float fx, float fy, float fz,
                                              bool valid)
{
    float4 v[8];
#pragma unroll
    for (int c = 0; c < 8; c++) {
        v[c] = ldg_tab128(fbase + ((size_t)slot[c] * 2 + h));
    }

    const float wx0 = 1.0f - fx, wx1 = fx;
    const float wy0 = 1.0f - fy, wy1 = fy;
    const float wz0 = 1.0f - fz, wz1 = fz;
    float w[8];
    w[0] = wx0 * wy0 * wz0;
    w[1] = wx1 * wy0 * wz0;
    w[2] = wx0 * wy1 * wz0;
    w[3] = wx1 * wy1 * wz0;
    w[4] = wx0 * wy0 * wz1;
    w[5] = wx1 * wy0 * wz1;
    w[6] = wx0 * wy1 * wz1;
    w[7] = wx1 * wy1 * wz1;

    float a0 = 0.f, a1 = 0.f, a2 = 0.f, a3 = 0.f;
#pragma unroll
    for (int c = 0; c < 8; c++) {
        const float wc = w[c];
        a0 = fmaf(wc, v[c].x, a0);
        a1 = fmaf(wc, v[c].y, a1);
        a2 = fmaf(wc, v[c].z, a2);
        a3 = fmaf(wc, v[c].w, a3);
    }
    if (valid) stg_stream(outp, make_float4(a0, a1, a2, a3));
}

// Pair-lane layout (measured best: 8 wf/point) with L2-prefetch pipelining:
// each thread serves 2 points; point 1's 8 table lines are prefetched into L2
// (no registers, no data-return wavefronts) before point 0's demand loads, so
// ~16 memory ops are in flight per thread without the R12 register blowup.
template <bool POW2>
__global__ __launch_bounds__(256)
void hash_interp_pf(const float* __restrict__ pts,
                    const float* __restrict__ feat,
                    float* __restrict__ out,
                    int n, unsigned buckets, unsigned mask)
{
    const unsigned lane = threadIdx.x & 31u;
    const int gwarp = (int)((blockIdx.x * blockDim.x + threadIdx.x) >> 5);
    const unsigned h = lane & 1u;

    const float4* fbase = reinterpret_cast<const float4*>(feat);
    float4* obase = reinterpret_cast<float4*>(out);

    const int pid0 = gwarp * 32 + (int)(lane >> 1);   // 32 points per warp
    const int pid1 = pid0 + 16;
    const bool valid0 = (pid0 < n);
    const bool valid1 = (pid1 < n);

    // setup both points (slots + fracs)
    unsigned slot0[8], slot1[8];
    float fx0, fy0, fz0, fx1, fy1, fz1;
    point_setup<POW2>(pts, valid0 ? pid0 : 0, buckets, mask, slot0, fx0, fy0, fz0);
    point_setup<POW2>(pts, valid1 ? pid1 : 0, buckets, mask, slot1, fx1, fy1, fz1);

    // prefetch point 1's table lines into L2; pair-lanes share each line so
    // only the h==0 lane issues (halves prefetch issue, same coverage).
    if (h == 0u) {
#pragma unroll
        for (int c = 0; c < 8; c++) {
            prefetch_l2(fbase + (size_t)slot1[c] * 2);
        }
    }

    // point 0: demand loads overlap the in-flight prefetches
    point_consume(fbase, obase + ((size_t)pid0 * 2 + h),
                  slot0, h, fx0, fy0, fz0, valid0);

    // point 1: lines now (mostly) L2-resident -> ~234cyc instead of ~600
    point_consume(fbase, obase + ((size_t)pid1 * 2 + h),
                  slot1, h, fx1, fy1, fz1, valid1);
}

extern "C" void kernel_launch(void* const* d_in, const int* in_sizes, int n_in,
                              void* d_out, int out_size)
{
    const float* pts  = (const float*)d_in[0];
    const float* feat = (const float*)d_in[1];
    float* out = (float*)d_out;

    int n = in_sizes[0] / 3;
    unsigned buckets = (unsigned)(in_sizes[1] / 8);
    unsigned mask = buckets - 1u;
    bool pow2 = (buckets & (buckets - 1u)) == 0u;

    // 2 lanes/point, 2 points/thread -> 32 points per warp
    long long warps = ((long long)n + 31) / 32;
    long long threads_total = warps * 32;
    int threads = 256;
    int blocks = (int)((threads_total + threads - 1) / threads);

    if (pow2) {
        hash_interp_pf<true><<<blocks, threads>>>(pts, feat, out, n, buckets, mask);
    } else {
        hash_interp_pf<false><<<blocks, threads>>>(pts, feat, out, n, buckets, mask);
    }
}